// round 1
// baseline (speedup 1.0000x reference)
#include <cuda_runtime.h>

#define NN 8192
#define DD 64
#define NEG_INV_EPS (-10.0f)

static __device__ float  g_C[(size_t)NN * NN];   // 256 MB pairwise distances
static __device__ float  g_u[NN];
static __device__ float  g_v[NN];
static __device__ float  g_pn[NN];
static __device__ float  g_qn[NN];
static __device__ double g_loss;

__device__ __forceinline__ float block_reduce(float v) {
    __shared__ float sh[8];
    int lane = threadIdx.x & 31, w = threadIdx.x >> 5;
    #pragma unroll
    for (int o = 16; o; o >>= 1) v += __shfl_down_sync(0xFFFFFFFFu, v, o);
    if (lane == 0) sh[w] = v;
    __syncthreads();
    if (w == 0) {
        v = (lane < 8) ? sh[lane] : 0.0f;
        #pragma unroll
        for (int o = 4; o; o >>= 1) v += __shfl_down_sync(0xFFFFFFFFu, v, o);
    }
    return v;  // valid on thread 0
}

// Row norms of P and Q, init u = 1/D, zero the loss accumulator.
__global__ void prep_kernel(const float* __restrict__ P, const float* __restrict__ Q) {
    int i = blockIdx.x * blockDim.x + threadIdx.x;
    if (i == 0) g_loss = 0.0;
    if (i < NN) {
        const float4* p = (const float4*)(P + (size_t)i * DD);
        const float4* q = (const float4*)(Q + (size_t)i * DD);
        float sp = 0.f, sq = 0.f;
        #pragma unroll
        for (int k = 0; k < DD / 4; ++k) {
            float4 a = p[k]; sp += a.x*a.x + a.y*a.y + a.z*a.z + a.w*a.w;
            float4 b = q[k]; sq += b.x*b.x + b.y*b.y + b.z*b.z + b.w*b.w;
        }
        g_pn[i] = sp;
        g_qn[i] = sq;
        g_u[i]  = 1.0f / 64.0f;   // reference: ones(N)/D, D=64
    }
}

// C[i][j] = sqrt(max(|P_i|^2 + |Q_j|^2 - 2 P_i.Q_j, 0)); 64x64 tile per block,
// 4x4 micro-tile per thread, shared tiles stored k-major for LDS.128 reads.
__global__ __launch_bounds__(256) void cdist_kernel(const float* __restrict__ P,
                                                    const float* __restrict__ Q) {
    __shared__ __align__(16) float Ps[64][68];
    __shared__ __align__(16) float Qs[64][68];
    const int bi = blockIdx.y * 64, bj = blockIdx.x * 64;
    const int tid = threadIdx.y * 16 + threadIdx.x;

    #pragma unroll
    for (int r = 0; r < 4; ++r) {
        int idx = tid + r * 256;          // 0..1023
        int row = idx >> 4;               // 0..63
        int c4  = (idx & 15) << 2;        // 0,4,...,60
        float4 a = *(const float4*)(P + (size_t)(bi + row) * DD + c4);
        Ps[c4 + 0][row] = a.x; Ps[c4 + 1][row] = a.y;
        Ps[c4 + 2][row] = a.z; Ps[c4 + 3][row] = a.w;
        float4 b = *(const float4*)(Q + (size_t)(bj + row) * DD + c4);
        Qs[c4 + 0][row] = b.x; Qs[c4 + 1][row] = b.y;
        Qs[c4 + 2][row] = b.z; Qs[c4 + 3][row] = b.w;
    }
    __syncthreads();

    const int ty4 = threadIdx.y * 4, tx4 = threadIdx.x * 4;
    float acc[4][4] = {};
    #pragma unroll
    for (int k = 0; k < 64; ++k) {
        float4 a = *(const float4*)&Ps[k][ty4];
        float4 b = *(const float4*)&Qs[k][tx4];
        float av[4] = {a.x, a.y, a.z, a.w};
        float bv[4] = {b.x, b.y, b.z, b.w};
        #pragma unroll
        for (int i = 0; i < 4; ++i)
            #pragma unroll
            for (int j = 0; j < 4; ++j)
                acc[i][j] += av[i] * bv[j];
    }

    float4 qn = *(const float4*)&g_qn[bj + tx4];
    float qv[4] = {qn.x, qn.y, qn.z, qn.w};
    #pragma unroll
    for (int i = 0; i < 4; ++i) {
        size_t row = (size_t)(bi + ty4 + i);
        float pn = g_pn[row];
        float4 c;
        float* cp = &c.x;
        #pragma unroll
        for (int j = 0; j < 4; ++j) {
            float sq = pn + qv[j] - 2.0f * acc[i][j];
            cp[j] = sqrtf(fmaxf(sq, 0.0f));
        }
        *(float4*)(g_C + row * NN + bj + tx4) = c;
    }
}

// One Sinkhorn half-step: y_i = 1 / sum_j exp(-C_ij/eps) * x_j
// phase 0: x = u, y = v ; phase 1: x = v, y = u.
__global__ __launch_bounds__(256) void sink_kernel(int phase) {
    const float* __restrict__ x = phase ? g_v : g_u;
    float* __restrict__       y = phase ? g_u : g_v;
    const size_t row = blockIdx.x;
    const float4* __restrict__ C4 = (const float4*)(g_C + row * NN);
    const float4* __restrict__ x4 = (const float4*)x;
    float s = 0.f;
    #pragma unroll 4
    for (int j = threadIdx.x; j < NN / 4; j += 256) {
        float4 c = C4[j];
        float4 xv = x4[j];
        s += __expf(c.x * NEG_INV_EPS) * xv.x
           + __expf(c.y * NEG_INV_EPS) * xv.y
           + __expf(c.z * NEG_INV_EPS) * xv.z
           + __expf(c.w * NEG_INV_EPS) * xv.w;
    }
    s = block_reduce(s);
    if (threadIdx.x == 0) y[row] = 1.0f / s;
}

// loss = sum_ij u_i * exp(-C_ij/eps) * v_j * C_ij
__global__ __launch_bounds__(256) void loss_kernel() {
    const size_t row = blockIdx.x;
    const float4* __restrict__ C4 = (const float4*)(g_C + row * NN);
    const float4* __restrict__ v4 = (const float4*)g_v;
    float s = 0.f;
    #pragma unroll 4
    for (int j = threadIdx.x; j < NN / 4; j += 256) {
        float4 c = C4[j];
        float4 vv = v4[j];
        s += __expf(c.x * NEG_INV_EPS) * vv.x * c.x
           + __expf(c.y * NEG_INV_EPS) * vv.y * c.y
           + __expf(c.z * NEG_INV_EPS) * vv.z * c.z
           + __expf(c.w * NEG_INV_EPS) * vv.w * c.w;
    }
    s = block_reduce(s);
    if (threadIdx.x == 0) atomicAdd(&g_loss, (double)(s * g_u[row]));
}

__global__ void out_kernel(float* out) {
    if (threadIdx.x == 0) out[0] = (float)g_loss;
}

extern "C" void kernel_launch(void* const* d_in, const int* in_sizes, int n_in,
                              void* d_out, int out_size) {
    const float* P = (const float*)d_in[0];
    const float* Q = (const float*)d_in[1];
    prep_kernel<<<(NN + 255) / 256, 256>>>(P, Q);
    cdist_kernel<<<dim3(NN / 64, NN / 64), dim3(16, 16)>>>(P, Q);
    for (int it = 0; it < 5; ++it) {
        sink_kernel<<<NN, 256>>>(0);
        sink_kernel<<<NN, 256>>>(1);
    }
    loss_kernel<<<NN, 256>>>();
    out_kernel<<<1, 1>>>((float*)d_out);
}

// round 2
// speedup vs baseline: 1.2354x; 1.2354x over previous
#include <cuda_runtime.h>
#include <cuda_fp16.h>

#define NN 8192
#define DD 64
#define NEG_INV_EPS (-10.0f)

static __device__ __half g_C[(size_t)NN * NN];   // 128 MB pairwise distances (fp16)
static __device__ float  g_u[NN];
static __device__ float  g_v[NN];
static __device__ float  g_pn[NN];
static __device__ float  g_qn[NN];
static __device__ double g_loss;

__device__ __forceinline__ float block_reduce(float v) {
    __shared__ float sh[8];
    int lane = threadIdx.x & 31, w = threadIdx.x >> 5;
    #pragma unroll
    for (int o = 16; o; o >>= 1) v += __shfl_down_sync(0xFFFFFFFFu, v, o);
    if (lane == 0) sh[w] = v;
    __syncthreads();
    if (w == 0) {
        v = (lane < 8) ? sh[lane] : 0.0f;
        #pragma unroll
        for (int o = 4; o; o >>= 1) v += __shfl_down_sync(0xFFFFFFFFu, v, o);
    }
    return v;  // valid on thread 0
}

// Row norms of P and Q, init u = 1/D, zero the loss accumulator.
__global__ void prep_kernel(const float* __restrict__ P, const float* __restrict__ Q) {
    int i = blockIdx.x * blockDim.x + threadIdx.x;
    if (i == 0) g_loss = 0.0;
    if (i < NN) {
        const float4* p = (const float4*)(P + (size_t)i * DD);
        const float4* q = (const float4*)(Q + (size_t)i * DD);
        float sp = 0.f, sq = 0.f;
        #pragma unroll
        for (int k = 0; k < DD / 4; ++k) {
            float4 a = p[k]; sp += a.x*a.x + a.y*a.y + a.z*a.z + a.w*a.w;
            float4 b = q[k]; sq += b.x*b.x + b.y*b.y + b.z*b.z + b.w*b.w;
        }
        g_pn[i] = sp;
        g_qn[i] = sq;
        g_u[i]  = 1.0f / 64.0f;   // reference: ones(N)/D, D=64
    }
}

// C[i][j] = sqrt(max(|P_i|^2 + |Q_j|^2 - 2 P_i.Q_j, 0)); 64x64 tile per block,
// 4x4 micro-tile per thread, shared tiles stored k-major for LDS.128 reads.
__global__ __launch_bounds__(256) void cdist_kernel(const float* __restrict__ P,
                                                    const float* __restrict__ Q) {
    __shared__ __align__(16) float Ps[64][68];
    __shared__ __align__(16) float Qs[64][68];
    const int bi = blockIdx.y * 64, bj = blockIdx.x * 64;
    const int tid = threadIdx.y * 16 + threadIdx.x;

    #pragma unroll
    for (int r = 0; r < 4; ++r) {
        int idx = tid + r * 256;          // 0..1023
        int row = idx >> 4;               // 0..63
        int c4  = (idx & 15) << 2;        // 0,4,...,60
        float4 a = *(const float4*)(P + (size_t)(bi + row) * DD + c4);
        Ps[c4 + 0][row] = a.x; Ps[c4 + 1][row] = a.y;
        Ps[c4 + 2][row] = a.z; Ps[c4 + 3][row] = a.w;
        float4 b = *(const float4*)(Q + (size_t)(bj + row) * DD + c4);
        Qs[c4 + 0][row] = b.x; Qs[c4 + 1][row] = b.y;
        Qs[c4 + 2][row] = b.z; Qs[c4 + 3][row] = b.w;
    }
    __syncthreads();

    const int ty4 = threadIdx.y * 4, tx4 = threadIdx.x * 4;
    float acc[4][4] = {};
    #pragma unroll
    for (int k = 0; k < 64; ++k) {
        float4 a = *(const float4*)&Ps[k][ty4];
        float4 b = *(const float4*)&Qs[k][tx4];
        float av[4] = {a.x, a.y, a.z, a.w};
        float bv[4] = {b.x, b.y, b.z, b.w};
        #pragma unroll
        for (int i = 0; i < 4; ++i)
            #pragma unroll
            for (int j = 0; j < 4; ++j)
                acc[i][j] += av[i] * bv[j];
    }

    float4 qn = *(const float4*)&g_qn[bj + tx4];
    float qv[4] = {qn.x, qn.y, qn.z, qn.w};
    #pragma unroll
    for (int i = 0; i < 4; ++i) {
        size_t row = (size_t)(bi + ty4 + i);
        float pn = g_pn[row];
        float c[4];
        #pragma unroll
        for (int j = 0; j < 4; ++j) {
            float sq = pn + qv[j] - 2.0f * acc[i][j];
            c[j] = sqrtf(fmaxf(sq, 0.0f));
        }
        __half2 h01 = __floats2half2_rn(c[0], c[1]);
        __half2 h23 = __floats2half2_rn(c[2], c[3]);
        uint2 pk;
        pk.x = *(unsigned*)&h01;
        pk.y = *(unsigned*)&h23;
        *(uint2*)(g_C + row * NN + bj + tx4) = pk;
    }
}

// One Sinkhorn half-step: y_i = 1 / sum_j exp(-C_ij/eps) * x_j
// phase 0: x = u, y = v ; phase 1: x = v, y = u.
__global__ __launch_bounds__(256) void sink_kernel(int phase) {
    const float* __restrict__ x = phase ? g_v : g_u;
    float* __restrict__       y = phase ? g_u : g_v;
    const size_t row = blockIdx.x;
    const uint4* __restrict__ C8 = (const uint4*)(g_C + row * NN);
    const float4* __restrict__ x4 = (const float4*)x;
    float s = 0.f;
    #pragma unroll 4
    for (int j = threadIdx.x; j < NN / 8; j += 256) {
        uint4 c = C8[j];
        float2 f0 = __half22float2(*(__half2*)&c.x);
        float2 f1 = __half22float2(*(__half2*)&c.y);
        float2 f2 = __half22float2(*(__half2*)&c.z);
        float2 f3 = __half22float2(*(__half2*)&c.w);
        float4 xa = x4[2 * j], xb = x4[2 * j + 1];
        s += __expf(f0.x * NEG_INV_EPS) * xa.x
           + __expf(f0.y * NEG_INV_EPS) * xa.y
           + __expf(f1.x * NEG_INV_EPS) * xa.z
           + __expf(f1.y * NEG_INV_EPS) * xa.w
           + __expf(f2.x * NEG_INV_EPS) * xb.x
           + __expf(f2.y * NEG_INV_EPS) * xb.y
           + __expf(f3.x * NEG_INV_EPS) * xb.z
           + __expf(f3.y * NEG_INV_EPS) * xb.w;
    }
    s = block_reduce(s);
    if (threadIdx.x == 0) y[row] = 1.0f / s;
}

// loss = sum_ij u_i * exp(-C_ij/eps) * v_j * C_ij
__global__ __launch_bounds__(256) void loss_kernel() {
    const size_t row = blockIdx.x;
    const uint4* __restrict__ C8 = (const uint4*)(g_C + row * NN);
    const float4* __restrict__ v4 = (const float4*)g_v;
    float s = 0.f;
    #pragma unroll 4
    for (int j = threadIdx.x; j < NN / 8; j += 256) {
        uint4 c = C8[j];
        float2 f0 = __half22float2(*(__half2*)&c.x);
        float2 f1 = __half22float2(*(__half2*)&c.y);
        float2 f2 = __half22float2(*(__half2*)&c.z);
        float2 f3 = __half22float2(*(__half2*)&c.w);
        float4 va = v4[2 * j], vb = v4[2 * j + 1];
        s += __expf(f0.x * NEG_INV_EPS) * va.x * f0.x
           + __expf(f0.y * NEG_INV_EPS) * va.y * f0.y
           + __expf(f1.x * NEG_INV_EPS) * va.z * f1.x
           + __expf(f1.y * NEG_INV_EPS) * va.w * f1.y
           + __expf(f2.x * NEG_INV_EPS) * vb.x * f2.x
           + __expf(f2.y * NEG_INV_EPS) * vb.y * f2.y
           + __expf(f3.x * NEG_INV_EPS) * vb.z * f3.x
           + __expf(f3.y * NEG_INV_EPS) * vb.w * f3.y;
    }
    s = block_reduce(s);
    if (threadIdx.x == 0) atomicAdd(&g_loss, (double)(s * g_u[row]));
}

__global__ void out_kernel(float* out) {
    if (threadIdx.x == 0) out[0] = (float)g_loss;
}

extern "C" void kernel_launch(void* const* d_in, const int* in_sizes, int n_in,
                              void* d_out, int out_size) {
    const float* P = (const float*)d_in[0];
    const float* Q = (const float*)d_in[1];
    prep_kernel<<<(NN + 255) / 256, 256>>>(P, Q);
    cdist_kernel<<<dim3(NN / 64, NN / 64), dim3(16, 16)>>>(P, Q);
    for (int it = 0; it < 5; ++it) {
        sink_kernel<<<NN, 256>>>(0);
        sink_kernel<<<NN, 256>>>(1);
    }
    loss_kernel<<<NN, 256>>>();
    out_kernel<<<1, 1>>>((float*)d_out);
}

// round 4
// speedup vs baseline: 2.0713x; 1.6767x over previous
#include <cuda_runtime.h>
#include <cuda_fp16.h>
#include <cstdint>

#define NN 8192
#define DD 64

static __device__ __half g_K[(size_t)NN * NN];   // 128 MB: K = exp(-C/eps), fp16
static __device__ float  g_u[NN];
static __device__ float  g_v[NN];
static __device__ float  g_pn[NN];
static __device__ float  g_qn[NN];
static __device__ double g_loss;

__device__ __forceinline__ float fsqrt_ap(float x) { float r; asm("sqrt.approx.f32 %0, %1;" : "=f"(r) : "f"(x)); return r; }
__device__ __forceinline__ float fex2(float x)     { float r; asm("ex2.approx.f32 %0, %1;"  : "=f"(r) : "f"(x)); return r; }
__device__ __forceinline__ float flg2(float x)     { float r; asm("lg2.approx.f32 %0, %1;"  : "=f"(r) : "f"(x)); return r; }

__global__ void prep_kernel(const float* __restrict__ P, const float* __restrict__ Q) {
    int i = blockIdx.x * blockDim.x + threadIdx.x;
    if (i == 0) g_loss = 0.0;
    if (i < NN) {
        const float4* p = (const float4*)(P + (size_t)i * DD);
        const float4* q = (const float4*)(Q + (size_t)i * DD);
        float sp = 0.f, sq = 0.f;
        #pragma unroll
        for (int k = 0; k < DD / 4; ++k) {
            float4 a = p[k]; sp += a.x*a.x + a.y*a.y + a.z*a.z + a.w*a.w;
            float4 b = q[k]; sq += b.x*b.x + b.y*b.y + b.z*b.z + b.w*b.w;
        }
        g_pn[i] = sp;
        g_qn[i] = sq;
        g_u[i]  = 1.0f / 64.0f;   // reference: ones(N)/D, D=64
    }
}

// K[i][j] = exp(-sqrt(max(pn_i + qn_j - 2 P_i.Q_j, 0))/eps) via mma.sync m16n8k16.
// 128x128 tile per CTA, 8 warps in a 4x2 grid, each warp 32x64 (2x8 fragments).
#define LDSW 72   // smem row stride in halfs: 144B = 36 banks -> conflict-free frag reads
__global__ __launch_bounds__(256) void ck_kernel(const float* __restrict__ P,
                                                 const float* __restrict__ Q) {
    __shared__ __half Ps[128 * LDSW];
    __shared__ __half Qs[128 * LDSW];
    __shared__ float  s_pn[128], s_qn[128];

    const int bi = blockIdx.y * 128, bj = blockIdx.x * 128;
    const int tid = threadIdx.x;
    const int wid = tid >> 5, lane = tid & 31;
    const int g = lane >> 2, tq = lane & 3;
    const int mrow = (wid >> 1) * 32, ncol = (wid & 1) * 64;

    // Load tiles: fp32 gmem -> fp16 smem, k-contiguous rows
    #pragma unroll
    for (int r = 0; r < 8; ++r) {
        int idx = tid + r * 256;           // 0..2047
        int row = idx >> 4;                // 0..127
        int c4  = (idx & 15) << 2;         // 0..60
        float4 a = *(const float4*)(P + (size_t)(bi + row) * DD + c4);
        float4 b = *(const float4*)(Q + (size_t)(bj + row) * DD + c4);
        __half2 a01 = __floats2half2_rn(a.x, a.y), a23 = __floats2half2_rn(a.z, a.w);
        __half2 b01 = __floats2half2_rn(b.x, b.y), b23 = __floats2half2_rn(b.z, b.w);
        uint2 pa; pa.x = *(uint32_t*)&a01; pa.y = *(uint32_t*)&a23;
        uint2 pb; pb.x = *(uint32_t*)&b01; pb.y = *(uint32_t*)&b23;
        *(uint2*)(Ps + row * LDSW + c4) = pa;
        *(uint2*)(Qs + row * LDSW + c4) = pb;
    }
    if (tid < 128) {
        s_pn[tid] = g_pn[bi + tid];
        s_qn[tid] = g_qn[bj + tid];
    }
    __syncthreads();

    float acc[2][8][4];
    #pragma unroll
    for (int i = 0; i < 2; ++i)
        #pragma unroll
        for (int j = 0; j < 8; ++j)
            #pragma unroll
            for (int r = 0; r < 4; ++r) acc[i][j][r] = 0.f;

    #pragma unroll
    for (int ks = 0; ks < 4; ++ks) {
        const int k0 = ks * 16;
        uint32_t A[2][4], B[8][2];
        #pragma unroll
        for (int i = 0; i < 2; ++i) {
            const __half* base = Ps + (mrow + i * 16 + g) * LDSW + k0 + tq * 2;
            A[i][0] = *(const uint32_t*)(base);
            A[i][1] = *(const uint32_t*)(base + 8 * LDSW);
            A[i][2] = *(const uint32_t*)(base + 8);
            A[i][3] = *(const uint32_t*)(base + 8 * LDSW + 8);
        }
        #pragma unroll
        for (int j = 0; j < 8; ++j) {
            const __half* base = Qs + (ncol + j * 8 + g) * LDSW + k0 + tq * 2;
            B[j][0] = *(const uint32_t*)(base);
            B[j][1] = *(const uint32_t*)(base + 8);
        }
        #pragma unroll
        for (int i = 0; i < 2; ++i)
            #pragma unroll
            for (int j = 0; j < 8; ++j)
                asm volatile(
                    "mma.sync.aligned.m16n8k16.row.col.f32.f16.f16.f32 "
                    "{%0,%1,%2,%3}, {%4,%5,%6,%7}, {%8,%9}, {%0,%1,%2,%3};"
                    : "+f"(acc[i][j][0]), "+f"(acc[i][j][1]),
                      "+f"(acc[i][j][2]), "+f"(acc[i][j][3])
                    : "r"(A[i][0]), "r"(A[i][1]), "r"(A[i][2]), "r"(A[i][3]),
                      "r"(B[j][0]), "r"(B[j][1]));
    }

    // Epilogue: K = ex2(-log2(e)/eps * sqrt(max(pn+qn-2d, 0))), fp16 store
    #pragma unroll
    for (int i = 0; i < 2; ++i) {
        const int r0 = mrow + i * 16 + g;
        const float pn0 = s_pn[r0], pn1 = s_pn[r0 + 8];
        #pragma unroll
        for (int j = 0; j < 8; ++j) {
            const int c = ncol + j * 8 + tq * 2;
            const float qn0 = s_qn[c], qn1 = s_qn[c + 1];
            float s00 = fmaxf(pn0 + qn0 - 2.0f * acc[i][j][0], 0.f);
            float s01 = fmaxf(pn0 + qn1 - 2.0f * acc[i][j][1], 0.f);
            float s10 = fmaxf(pn1 + qn0 - 2.0f * acc[i][j][2], 0.f);
            float s11 = fmaxf(pn1 + qn1 - 2.0f * acc[i][j][3], 0.f);
            const float m = -14.4269504f;   // -log2(e)/eps
            float k00 = fex2(fsqrt_ap(s00) * m), k01 = fex2(fsqrt_ap(s01) * m);
            float k10 = fex2(fsqrt_ap(s10) * m), k11 = fex2(fsqrt_ap(s11) * m);
            __half2 h0 = __floats2half2_rn(k00, k01);
            __half2 h1 = __floats2half2_rn(k10, k11);
            *(uint32_t*)(g_K + (size_t)(bi + r0)     * NN + bj + c) = *(uint32_t*)&h0;
            *(uint32_t*)(g_K + (size_t)(bi + r0 + 8) * NN + bj + c) = *(uint32_t*)&h1;
        }
    }
}

__device__ __forceinline__ float block_reduce(float v) {
    __shared__ float sh[8];
    int lane = threadIdx.x & 31, w = threadIdx.x >> 5;
    #pragma unroll
    for (int o = 16; o; o >>= 1) v += __shfl_down_sync(0xFFFFFFFFu, v, o);
    if (lane == 0) sh[w] = v;
    __syncthreads();
    if (w == 0) {
        v = (lane < 8) ? sh[lane] : 0.0f;
        #pragma unroll
        for (int o = 4; o; o >>= 1) v += __shfl_down_sync(0xFFFFFFFFu, v, o);
    }
    return v;  // valid on thread 0
}

// One Sinkhorn half-step: y_i = 1 / sum_j K_ij * x_j  (pure streaming, no MUFU)
__global__ __launch_bounds__(256) void sink_kernel(int phase) {
    const float* __restrict__ x = phase ? g_v : g_u;
    float* __restrict__       y = phase ? g_u : g_v;
    const size_t row = blockIdx.x;
    const uint4* __restrict__ K8 = (const uint4*)(g_K + row * NN);
    const float4* __restrict__ x4 = (const float4*)x;
    float s = 0.f;
    #pragma unroll 4
    for (int j = threadIdx.x; j < NN / 8; j += 256) {
        uint4 k = K8[j];
        float2 f0 = __half22float2(*(__half2*)&k.x);
        float2 f1 = __half22float2(*(__half2*)&k.y);
        float2 f2 = __half22float2(*(__half2*)&k.z);
        float2 f3 = __half22float2(*(__half2*)&k.w);
        float4 xa = x4[2 * j], xb = x4[2 * j + 1];
        s += f0.x * xa.x + f0.y * xa.y + f1.x * xa.z + f1.y * xa.w
           + f2.x * xb.x + f2.y * xb.y + f3.x * xb.z + f3.y * xb.w;
    }
    s = block_reduce(s);
    if (threadIdx.x == 0) y[row] = 1.0f / s;
}

// loss = sum_ij u_i * K_ij * v_j * C_ij, with C = -eps * ln(K)
__global__ __launch_bounds__(256) void loss_kernel() {
    const size_t row = blockIdx.x;
    const uint4* __restrict__ K8 = (const uint4*)(g_K + row * NN);
    const float4* __restrict__ v4 = (const float4*)g_v;
    float s = 0.f;
    #pragma unroll 4
    for (int j = threadIdx.x; j < NN / 8; j += 256) {
        uint4 k = K8[j];
        float2 f0 = __half22float2(*(__half2*)&k.x);
        float2 f1 = __half22float2(*(__half2*)&k.y);
        float2 f2 = __half22float2(*(__half2*)&k.z);
        float2 f3 = __half22float2(*(__half2*)&k.w);
        float4 va = v4[2 * j], vb = v4[2 * j + 1];
        const float m = -0.069314718f;   // -eps * ln2
        s += f0.x * va.x * (m * flg2(f0.x))
           + f0.y * va.y * (m * flg2(f0.y))
           + f1.x * va.z * (m * flg2(f1.x))
           + f1.y * va.w * (m * flg2(f1.y))
           + f2.x * vb.x * (m * flg2(f2.x))
           + f2.y * vb.y * (m * flg2(f2.y))
           + f3.x * vb.z * (m * flg2(f3.x))
           + f3.y * vb.w * (m * flg2(f3.y));
    }
    s = block_reduce(s);
    if (threadIdx.x == 0) atomicAdd(&g_loss, (double)(s * g_u[row]));
}

__global__ void out_kernel(float* out) {
    if (threadIdx.x == 0) out[0] = (float)g_loss;
}

extern "C" void kernel_launch(void* const* d_in, const int* in_sizes, int n_in,
                              void* d_out, int out_size) {
    const float* P = (const float*)d_in[0];
    const float* Q = (const float*)d_in[1];
    prep_kernel<<<(NN + 255) / 256, 256>>>(P, Q);
    ck_kernel<<<dim3(NN / 128, NN / 128), 256>>>(P, Q);
    for (int it = 0; it < 5; ++it) {
        sink_kernel<<<NN, 256>>>(0);
        sink_kernel<<<NN, 256>>>(1);
    }
    loss_kernel<<<NN, 256>>>();
    out_kernel<<<1, 1>>>((float*)d_out);
}

// round 5
// speedup vs baseline: 2.2625x; 1.0923x over previous
#include <cuda_runtime.h>
#include <cuda_fp16.h>
#include <cstdint>

#define NN 8192
#define DD 64

static __device__ __half g_K[(size_t)NN * NN];   // 128 MB: K = exp(-C/eps), fp16
static __device__ float  g_u[NN];
static __device__ float  g_v[NN];
static __device__ float  g_pn[NN];
static __device__ float  g_qn[NN];
static __device__ double g_loss;

__device__ __forceinline__ float fsqrt_ap(float x) { float r; asm("sqrt.approx.f32 %0, %1;" : "=f"(r) : "f"(x)); return r; }
__device__ __forceinline__ float fex2(float x)     { float r; asm("ex2.approx.f32 %0, %1;"  : "=f"(r) : "f"(x)); return r; }
__device__ __forceinline__ float flg2(float x)     { float r; asm("lg2.approx.f32 %0, %1;"  : "=f"(r) : "f"(x)); return r; }

__global__ void prep_kernel(const float* __restrict__ P, const float* __restrict__ Q) {
    int i = blockIdx.x * blockDim.x + threadIdx.x;
    if (i == 0) g_loss = 0.0;
    if (i < NN) {
        const float4* p = (const float4*)(P + (size_t)i * DD);
        const float4* q = (const float4*)(Q + (size_t)i * DD);
        float sp = 0.f, sq = 0.f;
        #pragma unroll
        for (int k = 0; k < DD / 4; ++k) {
            float4 a = p[k]; sp += a.x*a.x + a.y*a.y + a.z*a.z + a.w*a.w;
            float4 b = q[k]; sq += b.x*b.x + b.y*b.y + b.z*b.z + b.w*b.w;
        }
        g_pn[i] = sp;
        g_qn[i] = sq;
        g_u[i]  = 1.0f / 64.0f;   // reference: ones(N)/D, D=64
    }
}

// K[i][j] = exp(-sqrt(max(pn_i + qn_j - 2 P_i.Q_j, 0))/eps) via mma.sync m16n8k16.
// 128x128 tile per CTA, 8 warps in a 4x2 grid, each warp 32x64 (2x8 fragments).
#define LDSW 72   // smem row stride in halfs: 144B -> conflict-free frag reads
__global__ __launch_bounds__(256) void ck_kernel(const float* __restrict__ P,
                                                 const float* __restrict__ Q) {
    __shared__ __half Ps[128 * LDSW];
    __shared__ __half Qs[128 * LDSW];
    __shared__ float  s_pn[128], s_qn[128];

    const int bi = blockIdx.y * 128, bj = blockIdx.x * 128;
    const int tid = threadIdx.x;
    const int wid = tid >> 5, lane = tid & 31;
    const int g = lane >> 2, tq = lane & 3;
    const int mrow = (wid >> 1) * 32, ncol = (wid & 1) * 64;

    #pragma unroll
    for (int r = 0; r < 8; ++r) {
        int idx = tid + r * 256;
        int row = idx >> 4;
        int c4  = (idx & 15) << 2;
        float4 a = *(const float4*)(P + (size_t)(bi + row) * DD + c4);
        float4 b = *(const float4*)(Q + (size_t)(bj + row) * DD + c4);
        __half2 a01 = __floats2half2_rn(a.x, a.y), a23 = __floats2half2_rn(a.z, a.w);
        __half2 b01 = __floats2half2_rn(b.x, b.y), b23 = __floats2half2_rn(b.z, b.w);
        uint2 pa; pa.x = *(uint32_t*)&a01; pa.y = *(uint32_t*)&a23;
        uint2 pb; pb.x = *(uint32_t*)&b01; pb.y = *(uint32_t*)&b23;
        *(uint2*)(Ps + row * LDSW + c4) = pa;
        *(uint2*)(Qs + row * LDSW + c4) = pb;
    }
    if (tid < 128) {
        s_pn[tid] = g_pn[bi + tid];
        s_qn[tid] = g_qn[bj + tid];
    }
    __syncthreads();

    float acc[2][8][4];
    #pragma unroll
    for (int i = 0; i < 2; ++i)
        #pragma unroll
        for (int j = 0; j < 8; ++j)
            #pragma unroll
            for (int r = 0; r < 4; ++r) acc[i][j][r] = 0.f;

    #pragma unroll
    for (int ks = 0; ks < 4; ++ks) {
        const int k0 = ks * 16;
        uint32_t A[2][4], B[8][2];
        #pragma unroll
        for (int i = 0; i < 2; ++i) {
            const __half* base = Ps + (mrow + i * 16 + g) * LDSW + k0 + tq * 2;
            A[i][0] = *(const uint32_t*)(base);
            A[i][1] = *(const uint32_t*)(base + 8 * LDSW);
            A[i][2] = *(const uint32_t*)(base + 8);
            A[i][3] = *(const uint32_t*)(base + 8 * LDSW + 8);
        }
        #pragma unroll
        for (int j = 0; j < 8; ++j) {
            const __half* base = Qs + (ncol + j * 8 + g) * LDSW + k0 + tq * 2;
            B[j][0] = *(const uint32_t*)(base);
            B[j][1] = *(const uint32_t*)(base + 8);
        }
        #pragma unroll
        for (int i = 0; i < 2; ++i)
            #pragma unroll
            for (int j = 0; j < 8; ++j)
                asm volatile(
                    "mma.sync.aligned.m16n8k16.row.col.f32.f16.f16.f32 "
                    "{%0,%1,%2,%3}, {%4,%5,%6,%7}, {%8,%9}, {%0,%1,%2,%3};"
                    : "+f"(acc[i][j][0]), "+f"(acc[i][j][1]),
                      "+f"(acc[i][j][2]), "+f"(acc[i][j][3])
                    : "r"(A[i][0]), "r"(A[i][1]), "r"(A[i][2]), "r"(A[i][3]),
                      "r"(B[j][0]), "r"(B[j][1]));
    }

    #pragma unroll
    for (int i = 0; i < 2; ++i) {
        const int r0 = mrow + i * 16 + g;
        const float pn0 = s_pn[r0], pn1 = s_pn[r0 + 8];
        #pragma unroll
        for (int j = 0; j < 8; ++j) {
            const int c = ncol + j * 8 + tq * 2;
            const float qn0 = s_qn[c], qn1 = s_qn[c + 1];
            float s00 = fmaxf(pn0 + qn0 - 2.0f * acc[i][j][0], 0.f);
            float s01 = fmaxf(pn0 + qn1 - 2.0f * acc[i][j][1], 0.f);
            float s10 = fmaxf(pn1 + qn0 - 2.0f * acc[i][j][2], 0.f);
            float s11 = fmaxf(pn1 + qn1 - 2.0f * acc[i][j][3], 0.f);
            const float m = -14.4269504f;   // -log2(e)/eps
            float k00 = fex2(fsqrt_ap(s00) * m), k01 = fex2(fsqrt_ap(s01) * m);
            float k10 = fex2(fsqrt_ap(s10) * m), k11 = fex2(fsqrt_ap(s11) * m);
            __half2 h0 = __floats2half2_rn(k00, k01);
            __half2 h1 = __floats2half2_rn(k10, k11);
            *(uint32_t*)(g_K + (size_t)(bi + r0)     * NN + bj + c) = *(uint32_t*)&h0;
            *(uint32_t*)(g_K + (size_t)(bi + r0 + 8) * NN + bj + c) = *(uint32_t*)&h1;
        }
    }
}

// One Sinkhorn half-step, warp-per-row: y_row = 1 / sum_j K_rj * x_j.
// 8 warps/CTA, no smem, no block barrier — warp shuffle reduce only.
__global__ __launch_bounds__(256) void sink_kernel(int phase) {
    const float* __restrict__ x = phase ? g_v : g_u;
    float* __restrict__       y = phase ? g_u : g_v;
    const int row  = (blockIdx.x << 3) + (threadIdx.x >> 5);
    const int lane = threadIdx.x & 31;
    const uint4*  __restrict__ K8 = (const uint4*)(g_K + (size_t)row * NN);
    const float4* __restrict__ x4 = (const float4*)x;
    float s = 0.f;
    #pragma unroll 4
    for (int i = lane; i < NN / 8; i += 32) {
        uint4 k = K8[i];
        float2 f0 = __half22float2(*(__half2*)&k.x);
        float2 f1 = __half22float2(*(__half2*)&k.y);
        float2 f2 = __half22float2(*(__half2*)&k.z);
        float2 f3 = __half22float2(*(__half2*)&k.w);
        float4 xa = x4[2 * i], xb = x4[2 * i + 1];
        s += f0.x * xa.x + f0.y * xa.y + f1.x * xa.z + f1.y * xa.w
           + f2.x * xb.x + f2.y * xb.y + f3.x * xb.z + f3.y * xb.w;
    }
    #pragma unroll
    for (int o = 16; o; o >>= 1) s += __shfl_down_sync(0xFFFFFFFFu, s, o);
    if (lane == 0) y[row] = 1.0f / s;
}

// Fused final half-step + loss, warp-per-row:
//   s1 = sum_j K_rj v_j          -> u_r = 1/s1
//   s2 = sum_j K_rj v_j C_rj     (C = -eps ln K)
//   loss += s2 / s1
__global__ __launch_bounds__(256) void fused_loss_kernel() {
    const int row  = (blockIdx.x << 3) + (threadIdx.x >> 5);
    const int lane = threadIdx.x & 31;
    const int wid  = threadIdx.x >> 5;
    const uint4*  __restrict__ K8 = (const uint4*)(g_K + (size_t)row * NN);
    const float4* __restrict__ v4 = (const float4*)g_v;
    float s1 = 0.f, s2 = 0.f;
    const float m = -0.069314718f;   // -eps * ln2
    #pragma unroll 2
    for (int i = lane; i < NN / 8; i += 32) {
        uint4 k = K8[i];
        float2 f0 = __half22float2(*(__half2*)&k.x);
        float2 f1 = __half22float2(*(__half2*)&k.y);
        float2 f2 = __half22float2(*(__half2*)&k.z);
        float2 f3 = __half22float2(*(__half2*)&k.w);
        float4 va = v4[2 * i], vb = v4[2 * i + 1];
        float t0 = f0.x * va.x, t1 = f0.y * va.y, t2 = f1.x * va.z, t3 = f1.y * va.w;
        float t4 = f2.x * vb.x, t5 = f2.y * vb.y, t6 = f3.x * vb.z, t7 = f3.y * vb.w;
        s1 += t0 + t1 + t2 + t3 + t4 + t5 + t6 + t7;
        s2 += t0 * (m * flg2(f0.x)) + t1 * (m * flg2(f0.y))
            + t2 * (m * flg2(f1.x)) + t3 * (m * flg2(f1.y))
            + t4 * (m * flg2(f2.x)) + t5 * (m * flg2(f2.y))
            + t6 * (m * flg2(f3.x)) + t7 * (m * flg2(f3.y));
    }
    #pragma unroll
    for (int o = 16; o; o >>= 1) {
        s1 += __shfl_down_sync(0xFFFFFFFFu, s1, o);
        s2 += __shfl_down_sync(0xFFFFFFFFu, s2, o);
    }
    __shared__ double sh[8];
    if (lane == 0) sh[wid] = (double)(s2 / s1);
    __syncthreads();
    if (threadIdx.x == 0) {
        double t = sh[0] + sh[1] + sh[2] + sh[3] + sh[4] + sh[5] + sh[6] + sh[7];
        atomicAdd(&g_loss, t);
    }
}

__global__ void out_kernel(float* out) {
    if (threadIdx.x == 0) out[0] = (float)g_loss;
}

extern "C" void kernel_launch(void* const* d_in, const int* in_sizes, int n_in,
                              void* d_out, int out_size) {
    const float* P = (const float*)d_in[0];
    const float* Q = (const float*)d_in[1];
    prep_kernel<<<(NN + 255) / 256, 256>>>(P, Q);
    ck_kernel<<<dim3(NN / 128, NN / 128), 256>>>(P, Q);
    for (int it = 0; it < 4; ++it) {
        sink_kernel<<<NN / 8, 256>>>(0);
        sink_kernel<<<NN / 8, 256>>>(1);
    }
    sink_kernel<<<NN / 8, 256>>>(0);      // v of iteration 5
    fused_loss_kernel<<<NN / 8, 256>>>(); // final u half-step fused with loss
    out_kernel<<<1, 1>>>((float*)d_out);
}